// round 16
// baseline (speedup 1.0000x reference)
#include <cuda_runtime.h>
#include <cuda_fp16.h>
#include <cstdint>
#include <cstddef>

#define NTOK 8192
#define DIN  4096
#define DOUT 4096

// -------- device scratch --------
__device__ __half g_xh[(size_t)NTOK * DIN];    // fp16(x)
__device__ __half g_Wv2[(size_t)512 * DIN];    // [s 512][k 4096]  fp16(sign(V_b)*v2_b[k])
__device__ __half g_Wu2[(size_t)DOUT * 512];   // [n 4096][k 512]  fp16(sign(U_b)*u1_b[n])
__device__ __half g_h[(size_t)NTOK * 512];     // fp16 intermediate (v1*u2 applied)

// -------- helpers --------
__device__ __forceinline__ uint32_t smem_u32(const void* p) {
    uint32_t a;
    asm("{ .reg .u64 t; cvta.to.shared.u64 t, %1; cvt.u32.u64 %0, t; }" : "=r"(a) : "l"(p));
    return a;
}
__device__ __forceinline__ void cpa16(uint32_t dst, const void* src) {
    asm volatile("cp.async.cg.shared.global [%0], [%1], 16;" :: "r"(dst), "l"(src) : "memory");
}
#define CP_COMMIT() asm volatile("cp.async.commit_group;" ::: "memory")
#define CP_WAIT2()  asm volatile("cp.async.wait_group 2;" ::: "memory")

// fp16-accumulator mma: D,C are 2 x b32 (4 halves)
__device__ __forceinline__ void mma_f16acc(uint32_t* c, const uint32_t* a, uint32_t b0, uint32_t b1) {
    asm volatile(
        "mma.sync.aligned.m16n8k16.row.col.f16.f16.f16.f16 "
        "{%0,%1}, {%2,%3,%4,%5}, {%6,%7}, {%0,%1};"
        : "+r"(c[0]), "+r"(c[1])
        : "r"(a[0]), "r"(a[1]), "r"(a[2]), "r"(a[3]), "r"(b0), "r"(b1));
}
#define LDSM_X4(r0, r1, r2, r3, addr) \
    asm volatile("ldmatrix.sync.aligned.m8n8.x4.shared.b16 {%0,%1,%2,%3}, [%4];" \
                 : "=r"(r0), "=r"(r1), "=r"(r2), "=r"(r3) : "r"(addr))

// flush fp16 accumulators into fp32 shadow, zero fp16
#define FLUSH()                                                                   \
    do {                                                                          \
        _Pragma("unroll")                                                         \
        for (int mt = 0; mt < 2; mt++)                                            \
            _Pragma("unroll")                                                     \
            for (int nt = 0; nt < 8; nt++) {                                      \
                __half2 l = *reinterpret_cast<__half2*>(&hacc[mt][nt][0]);        \
                __half2 h = *reinterpret_cast<__half2*>(&hacc[mt][nt][1]);        \
                float2 lf = __half22float2(l), hf = __half22float2(h);            \
                facc[mt][nt][0] += lf.x; facc[mt][nt][1] += lf.y;                 \
                facc[mt][nt][2] += hf.x; facc[mt][nt][3] += hf.y;                 \
                hacc[mt][nt][0] = 0u; hacc[mt][nt][1] = 0u;                       \
            }                                                                     \
    } while (0)

// -------- smem geometry --------
// ktile = 32 halves (64B data), row stride 80B (conflict-free).
// A tile: 128 rows x 80B -> 10240B; B tile: 128 rows x 80B -> 10240B
// stage = 20480B, 4 stages = 81920B -> 2 CTAs/SM
#define BOFF 10240
#define STG  20480
#define GSMEM (4 * STG + 512)

// -------- kc: x -> fp16 --------
__global__ void kc_kernel(const float* __restrict__ x) {
    size_t i = ((size_t)blockIdx.x * blockDim.x + threadIdx.x) * 8;
    if (i >= (size_t)NTOK * DIN) return;
    float4 a = *reinterpret_cast<const float4*>(x + i);
    float4 b = *reinterpret_cast<const float4*>(x + i + 4);
    __half2 h0 = __floats2half2_rn(a.x, a.y);
    __half2 h1 = __floats2half2_rn(a.z, a.w);
    __half2 h2 = __floats2half2_rn(b.x, b.y);
    __half2 h3 = __floats2half2_rn(b.z, b.w);
    uint2 o, o2;
    o.x  = *reinterpret_cast<uint32_t*>(&h0);
    o.y  = *reinterpret_cast<uint32_t*>(&h1);
    o2.x = *reinterpret_cast<uint32_t*>(&h2);
    o2.y = *reinterpret_cast<uint32_t*>(&h3);
    *reinterpret_cast<uint2*>(g_xh + i) = o;
    *reinterpret_cast<uint2*>(g_xh + i + 4) = o2;
}

// -------- kw: fold scales into sign weights (fp16) --------
__global__ void kw_kernel(const float* __restrict__ V,  const float* __restrict__ VR,
                          const float* __restrict__ U,  const float* __restrict__ UR,
                          const float* __restrict__ v2, const float* __restrict__ v2R,
                          const float* __restrict__ u1, const float* __restrict__ u1R) {
    int i = blockIdx.x * blockDim.x + threadIdx.x;
    if (i >= 512 * DIN) return;
    {
        int s = i >> 12, k = i & (DIN - 1);
        float w  = (s < 256) ? V[(size_t)s * DIN + k] : VR[(size_t)(s - 256) * DIN + k];
        float sv = (s < 256) ? v2[k] : v2R[k];
        float sg = (w > 0.f) ? 1.f : ((w < 0.f) ? -1.f : 0.f);
        g_Wv2[i] = __float2half(sg * sv);
    }
    {
        int n = i >> 9, kk = i & 511;
        float w  = (kk < 256) ? U[(size_t)n * 256 + kk] : UR[(size_t)n * 256 + (kk - 256)];
        float su = (kk < 256) ? u1[n] : u1R[n];
        float sg = (w > 0.f) ? 1.f : ((w < 0.f) ? -1.f : 0.f);
        g_Wu2[i] = __float2half(sg * su);
    }
}

// ldmatrix lane-address helpers (80B row stride, conflict-free)
__device__ __forceinline__ uint32_t a_lane_off(int wm, int lane) {
    return (uint32_t)((wm * 32 + (lane & 15)) * 80 + (lane >> 4) * 16);
}
__device__ __forceinline__ uint32_t b_lane_off(int wn, int lane) {
    return (uint32_t)((wn * 64 + ((lane >> 4) << 3) + (lane & 7)) * 80 + (((lane >> 3) & 1) << 4));
}

// mainloop body: fp16 accum
#define BODY(stg)                                                                     \
    do {                                                                              \
        _Pragma("unroll")                                                             \
        for (int s16 = 0; s16 < 2; s16++) {                                           \
            uint32_t a0[4], a1[4];                                                    \
            LDSM_X4(a0[0], a0[1], a0[2], a0[3], (stg) + aoff + s16 * 32);             \
            LDSM_X4(a1[0], a1[1], a1[2], a1[3], (stg) + aoff + 16 * 80 + s16 * 32);   \
            _Pragma("unroll")                                                         \
            for (int ntp = 0; ntp < 4; ntp++) {                                       \
                uint32_t b[4];                                                        \
                LDSM_X4(b[0], b[1], b[2], b[3], (stg) + boff + ntp * (16 * 80) + s16 * 32); \
                mma_f16acc(hacc[0][2 * ntp],     a0, b[0], b[1]);                     \
                mma_f16acc(hacc[1][2 * ntp],     a1, b[0], b[1]);                     \
                mma_f16acc(hacc[0][2 * ntp + 1], a0, b[2], b[3]);                     \
                mma_f16acc(hacc[1][2 * ntp + 1], a1, b[2], b[3]);                     \
            }                                                                         \
        }                                                                             \
    } while (0)

// -------- k1: h[m, 512] = fp16( (x @ Wv2^T) * (v1*u2) ) --------
// grid (64, 4): br = by>>1, nb = (by&1)*128. CTA 128x128, 8 warps of 32x64, ktile 32.
__global__ void __launch_bounds__(256, 2) k1_kernel(
    const float* __restrict__ v1a, const float* __restrict__ u2a,
    const float* __restrict__ v1b, const float* __restrict__ u2b)
{
    extern __shared__ char sm[];
    const uint32_t smb = smem_u32(sm);
    const int tid = threadIdx.x, warp = tid >> 5, lane = tid & 31;
    const int r = lane >> 2, q = lane & 3;
    const int wm = warp >> 1, wn = warp & 1;
    const int m0 = blockIdx.x * 128;
    const int by = blockIdx.y;
    const int br = by >> 1, nb = (by & 1) * 128;

    float* sc = reinterpret_cast<float*>(sm + 4 * STG);
    if (tid < 128) {
        const float* v1 = br ? v1b : v1a;
        const float* u2 = br ? u2b : u2a;
        sc[tid] = v1[nb + tid] * u2[nb + tid];
    }
    const int row = tid >> 1, half = tid & 1;
    const uint32_t aoff = a_lane_off(wm, lane);
    const uint32_t boff = b_lane_off(wn, lane) + BOFF;

    auto issue = [&](int j) {
        if (j < 128) {
            const int s4 = j & 3, k0 = j * 32;
            uint32_t xd = smb + s4 * STG + row * 80 + half * 32;
            const __half* xs = g_xh + (size_t)(m0 + row) * DIN + k0 + half * 16;
            cpa16(xd, xs);
            cpa16(xd + 16, xs + 8);
            uint32_t bd = smb + s4 * STG + BOFF + row * 80 + half * 32;
            const __half* bsrc = g_Wv2 + (size_t)(br * 256 + nb + row) * DIN + k0 + half * 16;
            cpa16(bd, bsrc);
            cpa16(bd + 16, bsrc + 8);
        }
        CP_COMMIT();
    };
    issue(0); issue(1); issue(2);

    float facc[2][8][4];
    uint32_t hacc[2][8][2];
#pragma unroll
    for (int a = 0; a < 2; a++)
#pragma unroll
        for (int b = 0; b < 8; b++) {
#pragma unroll
            for (int c = 0; c < 4; c++) facc[a][b][c] = 0.f;
            hacc[a][b][0] = 0u; hacc[a][b][1] = 0u;
        }

    for (int it = 0; it < 128; ++it) {
        CP_WAIT2();
        __syncthreads();
        issue(it + 3);
        const uint32_t stg = smb + (it & 3) * STG;
        BODY(stg);
        if ((it & 7) == 7) FLUSH();
    }

    // epilogue: scale by (v1*u2), convert fp16, store h
#pragma unroll
    for (int mt = 0; mt < 2; mt++) {
#pragma unroll
        for (int nt = 0; nt < 8; nt++) {
            const int rw = m0 + wm * 32 + mt * 16 + r;
            const int cl = wn * 64 + nt * 8 + 2 * q;
            const int col = br * 256 + nb + cl;
            const float s0 = sc[cl], s1 = sc[cl + 1];
            __half2 p0 = __floats2half2_rn(facc[mt][nt][0] * s0, facc[mt][nt][1] * s1);
            __half2 p1 = __floats2half2_rn(facc[mt][nt][2] * s0, facc[mt][nt][3] * s1);
            *reinterpret_cast<uint32_t*>(g_h + (size_t)rw * 512 + col) =
                *reinterpret_cast<uint32_t*>(&p0);
            *reinterpret_cast<uint32_t*>(g_h + (size_t)(rw + 8) * 512 + col) =
                *reinterpret_cast<uint32_t*>(&p1);
        }
    }
}

// -------- k2: y[m, n] = h @ Wu2^T + bias --------
// grid (64, 32). CTA 128x128, 8 warps of 32x64, K=512, ktile 32, 16 iters.
__global__ void __launch_bounds__(256, 2) k2_kernel(
    const float* __restrict__ bias, float* __restrict__ out)
{
    extern __shared__ char sm[];
    const uint32_t smb = smem_u32(sm);
    const int tid = threadIdx.x, warp = tid >> 5, lane = tid & 31;
    const int r = lane >> 2, q = lane & 3;
    const int wm = warp >> 1, wn = warp & 1;
    const int m0 = blockIdx.x * 128;
    const int n0 = blockIdx.y * 128;

    float* bs = reinterpret_cast<float*>(sm + 4 * STG);
    if (tid < 128) bs[tid] = bias[n0 + tid];
    const int row = tid >> 1, half = tid & 1;
    const uint32_t aoff = a_lane_off(wm, lane);
    const uint32_t boff = b_lane_off(wn, lane) + BOFF;

    auto issue = [&](int j) {
        if (j < 16) {
            const int s4 = j & 3, k0 = j * 32;
            uint32_t xd = smb + s4 * STG + row * 80 + half * 32;
            const __half* xs = g_h + (size_t)(m0 + row) * 512 + k0 + half * 16;
            cpa16(xd, xs);
            cpa16(xd + 16, xs + 8);
            uint32_t bd = smb + s4 * STG + BOFF + row * 80 + half * 32;
            const __half* bsrc = g_Wu2 + (size_t)(n0 + row) * 512 + k0 + half * 16;
            cpa16(bd, bsrc);
            cpa16(bd + 16, bsrc + 8);
        }
        CP_COMMIT();
    };
    issue(0); issue(1); issue(2);

    float facc[2][8][4];
    uint32_t hacc[2][8][2];
#pragma unroll
    for (int a = 0; a < 2; a++)
#pragma unroll
        for (int b = 0; b < 8; b++) {
#pragma unroll
            for (int c = 0; c < 4; c++) facc[a][b][c] = 0.f;
            hacc[a][b][0] = 0u; hacc[a][b][1] = 0u;
        }

    for (int it = 0; it < 16; ++it) {
        CP_WAIT2();
        __syncthreads();
        issue(it + 3);
        const uint32_t stg = smb + (it & 3) * STG;
        BODY(stg);
        if ((it & 7) == 7) FLUSH();
    }

    // epilogue: + bias (u1 folded into Wu2)
#pragma unroll
    for (int mt = 0; mt < 2; mt++) {
#pragma unroll
        for (int nt = 0; nt < 8; nt++) {
            const int rw = m0 + wm * 32 + mt * 16 + r;
            const int cl = wn * 64 + nt * 8 + 2 * q;
            const int col = n0 + cl;
            float2 p0, p1;
            p0.x = facc[mt][nt][0] + bs[cl];
            p0.y = facc[mt][nt][1] + bs[cl + 1];
            p1.x = facc[mt][nt][2] + bs[cl];
            p1.y = facc[mt][nt][3] + bs[cl + 1];
            *reinterpret_cast<float2*>(out + (size_t)rw * DOUT + col) = p0;
            *reinterpret_cast<float2*>(out + (size_t)(rw + 8) * DOUT + col) = p1;
        }
    }
}

extern "C" void kernel_launch(void* const* d_in, const int* in_sizes, int n_in,
                              void* d_out, int out_size) {
    const float* x    = (const float*)d_in[0];
    const float* V    = (const float*)d_in[1];
    const float* U    = (const float*)d_in[2];
    const float* v1   = (const float*)d_in[3];
    const float* v2   = (const float*)d_in[4];
    const float* u1   = (const float*)d_in[5];
    const float* u2   = (const float*)d_in[6];
    const float* VR   = (const float*)d_in[7];
    const float* UR   = (const float*)d_in[8];
    const float* v1R  = (const float*)d_in[9];
    const float* v2R  = (const float*)d_in[10];
    const float* u1R  = (const float*)d_in[11];
    const float* u2R  = (const float*)d_in[12];
    const float* bias = (const float*)d_in[13];
    float* out = (float*)d_out;

    static bool attr_set = false;
    if (!attr_set) {
        cudaFuncSetAttribute(k1_kernel, cudaFuncAttributeMaxDynamicSharedMemorySize, GSMEM);
        cudaFuncSetAttribute(k2_kernel, cudaFuncAttributeMaxDynamicSharedMemorySize, GSMEM);
        attr_set = true;
    }

    kc_kernel<<<(NTOK * (size_t)DIN) / (256 * 8), 256>>>(x);
    kw_kernel<<<8192, 256>>>(V, VR, U, UR, v2, v2R, u1, u1R);
    k1_kernel<<<dim3(NTOK / 128, 4), 256, GSMEM>>>(v1, u2, v1R, u2R);
    k2_kernel<<<dim3(NTOK / 128, DOUT / 128), 256, GSMEM>>>(bias, out);
}

// round 17
// speedup vs baseline: 1.1326x; 1.1326x over previous
#include <cuda_runtime.h>
#include <cuda_fp16.h>
#include <cstdint>
#include <cstddef>

#define NTOK 8192
#define DIN  4096
#define DOUT 4096

// -------- device scratch --------
__device__ __half g_xh[(size_t)NTOK * DIN];    // fp16(x)
__device__ __half g_Wv2[(size_t)512 * DIN];    // [s 512][k 4096]  fp16(sign(V_b)*v2_b[k])
__device__ __half g_Wu2[(size_t)DOUT * 512];   // [n 4096][k 512]  fp16(sign(U_b)*u1_b[n])
__device__ __half g_h[(size_t)NTOK * 512];     // fp16 intermediate (v1*u2 applied)

// -------- helpers --------
__device__ __forceinline__ uint32_t smem_u32(const void* p) {
    uint32_t a;
    asm("{ .reg .u64 t; cvta.to.shared.u64 t, %1; cvt.u32.u64 %0, t; }" : "=r"(a) : "l"(p));
    return a;
}
__device__ __forceinline__ void cpa16(uint32_t dst, const void* src) {
    asm volatile("cp.async.cg.shared.global [%0], [%1], 16;" :: "r"(dst), "l"(src) : "memory");
}
#define CP_COMMIT() asm volatile("cp.async.commit_group;" ::: "memory")
#define CP_WAIT2()  asm volatile("cp.async.wait_group 2;" ::: "memory")

__device__ __forceinline__ void mma_fp16(float* c, const uint32_t* a, uint32_t b0, uint32_t b1) {
    asm volatile(
        "mma.sync.aligned.m16n8k16.row.col.f32.f16.f16.f32 "
        "{%0,%1,%2,%3}, {%4,%5,%6,%7}, {%8,%9}, {%0,%1,%2,%3};"
        : "+f"(c[0]), "+f"(c[1]), "+f"(c[2]), "+f"(c[3])
        : "r"(a[0]), "r"(a[1]), "r"(a[2]), "r"(a[3]), "r"(b0), "r"(b1));
}
#define LDSM_X4(r0, r1, r2, r3, addr) \
    asm volatile("ldmatrix.sync.aligned.m8n8.x4.shared.b16 {%0,%1,%2,%3}, [%4];" \
                 : "=r"(r0), "=r"(r1), "=r"(r2), "=r"(r3) : "r"(addr))

// -------- smem geometry --------
// ktile = 32 halves (64B data), row stride 80B (conflict-free).
// A tile: 128 rows x 80B -> 10240B; B tile: 128 rows x 80B -> 10240B
// stage = 20480B, 4 stages = 81920B -> 2 CTAs/SM
#define BOFF 10240
#define STG  20480
#define GSMEM (4 * STG + 512)

// -------- kp: merged prep — x -> fp16 AND fold scales into sign weights --------
// grid 16384 x 256: gid < 4.19M handles an 8-elem x chunk; gid < 2.10M also folds weights.
__global__ void kp_kernel(const float* __restrict__ x,
                          const float* __restrict__ V,  const float* __restrict__ VR,
                          const float* __restrict__ U,  const float* __restrict__ UR,
                          const float* __restrict__ v2, const float* __restrict__ v2R,
                          const float* __restrict__ u1, const float* __restrict__ u1R) {
    const int gid = blockIdx.x * blockDim.x + threadIdx.x;

    // ---- x conversion: 8 elems per thread ----
    {
        size_t i = (size_t)gid * 8;
        if (i < (size_t)NTOK * DIN) {
            float4 a = *reinterpret_cast<const float4*>(x + i);
            float4 b = *reinterpret_cast<const float4*>(x + i + 4);
            __half2 h0 = __floats2half2_rn(a.x, a.y);
            __half2 h1 = __floats2half2_rn(a.z, a.w);
            __half2 h2 = __floats2half2_rn(b.x, b.y);
            __half2 h3 = __floats2half2_rn(b.z, b.w);
            uint2 o, o2;
            o.x  = *reinterpret_cast<uint32_t*>(&h0);
            o.y  = *reinterpret_cast<uint32_t*>(&h1);
            o2.x = *reinterpret_cast<uint32_t*>(&h2);
            o2.y = *reinterpret_cast<uint32_t*>(&h3);
            *reinterpret_cast<uint2*>(g_xh + i) = o;
            *reinterpret_cast<uint2*>(g_xh + i + 4) = o2;
        }
    }

    // ---- weight folding: 2 items (one per table) per thread for gid < 512*DIN/2? ----
    // 512*DIN = 2,097,152 items per table; handle 1 item of each table per thread
    // for gid < 2,097,152 (grid provides 4,194,304 threads; half participate).
    if (gid < 512 * DIN) {
        const int i = gid;
        {
            int s = i >> 12, k = i & (DIN - 1);
            float w  = (s < 256) ? V[(size_t)s * DIN + k] : VR[(size_t)(s - 256) * DIN + k];
            float sv = (s < 256) ? v2[k] : v2R[k];
            float sg = (w > 0.f) ? 1.f : ((w < 0.f) ? -1.f : 0.f);
            g_Wv2[i] = __float2half(sg * sv);
        }
        {
            int n = i >> 9, kk = i & 511;
            float w  = (kk < 256) ? U[(size_t)n * 256 + kk] : UR[(size_t)n * 256 + (kk - 256)];
            float su = (kk < 256) ? u1[n] : u1R[n];
            float sg = (w > 0.f) ? 1.f : ((w < 0.f) ? -1.f : 0.f);
            g_Wu2[i] = __float2half(sg * su);
        }
    }
}

// ldmatrix lane-address helpers (80B row stride, conflict-free)
__device__ __forceinline__ uint32_t a_lane_off(int wm, int lane) {
    return (uint32_t)((wm * 32 + (lane & 15)) * 80 + (lane >> 4) * 16);
}
__device__ __forceinline__ uint32_t b_lane_off(int wn, int lane) {
    return (uint32_t)((wn * 64 + ((lane >> 4) << 3) + (lane & 7)) * 80 + (((lane >> 3) & 1) << 4));
}

// -------- k1: h[m, 512] = fp16( (x @ Wv2^T) * (v1*u2) ) --------
// grid (64, 4): br = by>>1, nb = (by&1)*128. CTA 128x128, 8 warps of 32x64, ktile 32.
__global__ void __launch_bounds__(256, 2) k1_kernel(
    const float* __restrict__ v1a, const float* __restrict__ u2a,
    const float* __restrict__ v1b, const float* __restrict__ u2b)
{
    extern __shared__ char sm[];
    const uint32_t smb = smem_u32(sm);
    const int tid = threadIdx.x, warp = tid >> 5, lane = tid & 31;
    const int r = lane >> 2, q = lane & 3;
    const int wm = warp >> 1, wn = warp & 1;
    const int m0 = blockIdx.x * 128;
    const int by = blockIdx.y;
    const int br = by >> 1, nb = (by & 1) * 128;

    float* sc = reinterpret_cast<float*>(sm + 4 * STG);
    if (tid < 128) {
        const float* v1 = br ? v1b : v1a;
        const float* u2 = br ? u2b : u2a;
        sc[tid] = v1[nb + tid] * u2[nb + tid];
    }
    const int row = tid >> 1, half = tid & 1;
    const uint32_t aoff = a_lane_off(wm, lane);
    const uint32_t boff = b_lane_off(wn, lane) + BOFF;

    auto issue = [&](int j) {
        if (j < 128) {
            const int s4 = j & 3, k0 = j * 32;
            uint32_t xd = smb + s4 * STG + row * 80 + half * 32;
            const __half* xs = g_xh + (size_t)(m0 + row) * DIN + k0 + half * 16;
            cpa16(xd, xs);
            cpa16(xd + 16, xs + 8);
            uint32_t bd = smb + s4 * STG + BOFF + row * 80 + half * 32;
            const __half* bsrc = g_Wv2 + (size_t)(br * 256 + nb + row) * DIN + k0 + half * 16;
            cpa16(bd, bsrc);
            cpa16(bd + 16, bsrc + 8);
        }
        CP_COMMIT();
    };
    issue(0); issue(1); issue(2);

    float acc[2][8][4];
#pragma unroll
    for (int a = 0; a < 2; a++)
#pragma unroll
        for (int b = 0; b < 8; b++)
#pragma unroll
            for (int c = 0; c < 4; c++) acc[a][b][c] = 0.f;

    for (int it = 0; it < 128; ++it) {
        CP_WAIT2();
        __syncthreads();
        issue(it + 3);
        const uint32_t stg = smb + (it & 3) * STG;
#pragma unroll
        for (int s16 = 0; s16 < 2; s16++) {
            uint32_t a[2][4];
            LDSM_X4(a[0][0], a[0][1], a[0][2], a[0][3], stg + aoff + s16 * 32);
            LDSM_X4(a[1][0], a[1][1], a[1][2], a[1][3], stg + aoff + 16 * 80 + s16 * 32);
#pragma unroll
            for (int ntp = 0; ntp < 4; ntp++) {
                uint32_t b[4];
                LDSM_X4(b[0], b[1], b[2], b[3], stg + boff + ntp * (16 * 80) + s16 * 32);
                mma_fp16(acc[0][2 * ntp],     a[0], b[0], b[1]);
                mma_fp16(acc[1][2 * ntp],     a[1], b[0], b[1]);
                mma_fp16(acc[0][2 * ntp + 1], a[0], b[2], b[3]);
                mma_fp16(acc[1][2 * ntp + 1], a[1], b[2], b[3]);
            }
        }
    }

    // epilogue: scale by (v1*u2), convert fp16, store h
#pragma unroll
    for (int mt = 0; mt < 2; mt++) {
#pragma unroll
        for (int nt = 0; nt < 8; nt++) {
            const int rw = m0 + wm * 32 + mt * 16 + r;
            const int cl = wn * 64 + nt * 8 + 2 * q;
            const int col = br * 256 + nb + cl;
            const float s0 = sc[cl], s1 = sc[cl + 1];
            __half2 p0 = __floats2half2_rn(acc[mt][nt][0] * s0, acc[mt][nt][1] * s1);
            __half2 p1 = __floats2half2_rn(acc[mt][nt][2] * s0, acc[mt][nt][3] * s1);
            *reinterpret_cast<uint32_t*>(g_h + (size_t)rw * 512 + col) =
                *reinterpret_cast<uint32_t*>(&p0);
            *reinterpret_cast<uint32_t*>(g_h + (size_t)(rw + 8) * 512 + col) =
                *reinterpret_cast<uint32_t*>(&p1);
        }
    }
}

// -------- k2: y[m, n] = h @ Wu2^T + bias --------
// grid (64, 32). CTA 128x128, 8 warps of 32x64, K=512, ktile 32, 16 iters.
__global__ void __launch_bounds__(256, 2) k2_kernel(
    const float* __restrict__ bias, float* __restrict__ out)
{
    extern __shared__ char sm[];
    const uint32_t smb = smem_u32(sm);
    const int tid = threadIdx.x, warp = tid >> 5, lane = tid & 31;
    const int r = lane >> 2, q = lane & 3;
    const int wm = warp >> 1, wn = warp & 1;
    const int m0 = blockIdx.x * 128;
    const int n0 = blockIdx.y * 128;

    float* bs = reinterpret_cast<float*>(sm + 4 * STG);
    if (tid < 128) bs[tid] = bias[n0 + tid];
    const int row = tid >> 1, half = tid & 1;
    const uint32_t aoff = a_lane_off(wm, lane);
    const uint32_t boff = b_lane_off(wn, lane) + BOFF;

    auto issue = [&](int j) {
        if (j < 16) {
            const int s4 = j & 3, k0 = j * 32;
            uint32_t xd = smb + s4 * STG + row * 80 + half * 32;
            const __half* xs = g_h + (size_t)(m0 + row) * 512 + k0 + half * 16;
            cpa16(xd, xs);
            cpa16(xd + 16, xs + 8);
            uint32_t bd = smb + s4 * STG + BOFF + row * 80 + half * 32;
            const __half* bsrc = g_Wu2 + (size_t)(n0 + row) * 512 + k0 + half * 16;
            cpa16(bd, bsrc);
            cpa16(bd + 16, bsrc + 8);
        }
        CP_COMMIT();
    };
    issue(0); issue(1); issue(2);

    float acc[2][8][4];
#pragma unroll
    for (int a = 0; a < 2; a++)
#pragma unroll
        for (int b = 0; b < 8; b++)
#pragma unroll
            for (int c = 0; c < 4; c++) acc[a][b][c] = 0.f;

    for (int it = 0; it < 16; ++it) {
        CP_WAIT2();
        __syncthreads();
        issue(it + 3);
        const uint32_t stg = smb + (it & 3) * STG;
#pragma unroll
        for (int s16 = 0; s16 < 2; s16++) {
            uint32_t a[2][4];
            LDSM_X4(a[0][0], a[0][1], a[0][2], a[0][3], stg + aoff + s16 * 32);
            LDSM_X4(a[1][0], a[1][1], a[1][2], a[1][3], stg + aoff + 16 * 80 + s16 * 32);
#pragma unroll
            for (int ntp = 0; ntp < 4; ntp++) {
                uint32_t b[4];
                LDSM_X4(b[0], b[1], b[2], b[3], stg + boff + ntp * (16 * 80) + s16 * 32);
                mma_fp16(acc[0][2 * ntp],     a[0], b[0], b[1]);
                mma_fp16(acc[1][2 * ntp],     a[1], b[0], b[1]);
                mma_fp16(acc[0][2 * ntp + 1], a[0], b[2], b[3]);
                mma_fp16(acc[1][2 * ntp + 1], a[1], b[2], b[3]);
            }
        }
    }

    // epilogue: + bias (u1 folded into Wu2)
#pragma unroll
    for (int mt = 0; mt < 2; mt++) {
#pragma unroll
        for (int nt = 0; nt < 8; nt++) {
            const int rw = m0 + wm * 32 + mt * 16 + r;
            const int cl = wn * 64 + nt * 8 + 2 * q;
            const int col = n0 + cl;
            float2 p0, p1;
            p0.x = acc[mt][nt][0] + bs[cl];
            p0.y = acc[mt][nt][1] + bs[cl + 1];
            p1.x = acc[mt][nt][2] + bs[cl];
            p1.y = acc[mt][nt][3] + bs[cl + 1];
            *reinterpret_cast<float2*>(out + (size_t)rw * DOUT + col) = p0;
            *reinterpret_cast<float2*>(out + (size_t)(rw + 8) * DOUT + col) = p1;
        }
    }
}

extern "C" void kernel_launch(void* const* d_in, const int* in_sizes, int n_in,
                              void* d_out, int out_size) {
    const float* x    = (const float*)d_in[0];
    const float* V    = (const float*)d_in[1];
    const float* U    = (const float*)d_in[2];
    const float* v1   = (const float*)d_in[3];
    const float* v2   = (const float*)d_in[4];
    const float* u1   = (const float*)d_in[5];
    const float* u2   = (const float*)d_in[6];
    const float* VR   = (const float*)d_in[7];
    const float* UR   = (const float*)d_in[8];
    const float* v1R  = (const float*)d_in[9];
    const float* v2R  = (const float*)d_in[10];
    const float* u1R  = (const float*)d_in[11];
    const float* u2R  = (const float*)d_in[12];
    const float* bias = (const float*)d_in[13];
    float* out = (float*)d_out;

    static bool attr_set = false;
    if (!attr_set) {
        cudaFuncSetAttribute(k1_kernel, cudaFuncAttributeMaxDynamicSharedMemorySize, GSMEM);
        cudaFuncSetAttribute(k2_kernel, cudaFuncAttributeMaxDynamicSharedMemorySize, GSMEM);
        attr_set = true;
    }

    // merged prep: 4,194,304 threads (x: 33.55M elems / 8; weights: first 2.10M threads)
    kp_kernel<<<16384, 256>>>(x, V, VR, U, UR, v2, v2R, u1, u1R);
    k1_kernel<<<dim3(NTOK / 128, 4), 256, GSMEM>>>(v1, u2, v1R, u2R);
    k2_kernel<<<dim3(NTOK / 128, DOUT / 128), 256, GSMEM>>>(bias, out);
}